// round 3
// baseline (speedup 1.0000x reference)
#include <cuda_runtime.h>
#include <math.h>

#define Bt 8
#define Nn 4096
#define Dd 1024
#define Pp 16
#define ITERS 3
#define TN 128
#define DK 128
#define NT (Nn/TN)
#define XSTRIDE (DK+4)
#define LOG2PI 1.8378770664093453f

typedef unsigned long long u64;

__device__ __forceinline__ u64 pk2(float a, float b) {
    u64 r; asm("mov.b64 %0, {%1,%2};" : "=l"(r) : "f"(a), "f"(b)); return r;
}
__device__ __forceinline__ void upk2(u64 v, float& lo, float& hi) {
    asm("mov.b64 {%0,%1}, %2;" : "=f"(lo), "=f"(hi) : "l"(v));
}
__device__ __forceinline__ void fma2(u64& acc, u64 a, u64 b) {
    asm("fma.rn.f32x2 %0, %1, %2, %0;" : "+l"(acc) : "l"(a), "l"(b));
}
__device__ __forceinline__ u64 mul2(u64 a, u64 b) {
    u64 r; asm("mul.rn.f32x2 %0, %1, %2;" : "=l"(r) : "l"(a), "l"(b)); return r;
}

// persistent state / scratch (no allocations allowed)
__device__ float g_A[Bt*Dd*Pp];     // [b][d][p] = mu * invSigma
__device__ float g_I[Bt*Dd*Pp];     // [b][d][p] = invSigma
__device__ float g_cst[Bt*Pp];
__device__ float g_pi[Bt*Pp];
__device__ float g_mu[Bt*Pp*Dd];
__device__ float g_Sg[Bt*Pp*Dd];
__device__ float g_mV[Pp*Dd];       // V + m*m
__device__ float g_wsum[Bt*Pp];
__device__ float g_wx[Bt*Pp*Dd];
__device__ float g_wxx[Bt*Pp*Dd];

__global__ void k_init(const float* __restrict__ m, const float* __restrict__ V_) {
    int i = blockIdx.x * blockDim.x + threadIdx.x;
    if (i < Pp*Dd) {
        float v = 0.1f * log1pf(expf(V_[i]));   // EPS * softplus(V_)
        float mm = m[i];
        g_mV[i] = v + mm*mm;
        #pragma unroll
        for (int b = 0; b < Bt; b++) {
            g_mu[b*Pp*Dd + i] = mm;
            g_Sg[b*Pp*Dd + i] = v;
            g_wx[b*Pp*Dd + i] = 0.f;
            g_wxx[b*Pp*Dd + i] = 0.f;
        }
    }
    if (i < Bt*Pp) { g_pi[i] = 1.0f/Pp; g_wsum[i] = 0.f; }
}

__global__ void k_prep() {
    int b = blockIdx.x / Pp, p = blockIdx.x % Pp;
    __shared__ float red[256];
    float acc = 0.f;
    for (int d = threadIdx.x; d < Dd; d += 256) {
        float S  = g_Sg[(b*Pp + p)*Dd + d];
        float mu = g_mu[(b*Pp + p)*Dd + d];
        float inv = 1.0f / S;
        g_A[(b*Dd + d)*Pp + p] = mu * inv;
        g_I[(b*Dd + d)*Pp + p] = inv;
        acc += logf(S) + mu*mu*inv;
    }
    red[threadIdx.x] = acc; __syncthreads();
    for (int s = 128; s > 0; s >>= 1) {
        if (threadIdx.x < s) red[threadIdx.x] += red[threadIdx.x + s];
        __syncthreads();
    }
    if (threadIdx.x == 0)
        g_cst[b*Pp + p] = logf(g_pi[b*Pp + p]) - 0.5f * ((float)Dd * LOG2PI + red[0]);
}

__device__ __forceinline__ void load_xtile(float* xs, const float* __restrict__ dptr,
                                           int dc, int tid) {
    #pragma unroll
    for (int k = 0; k < 16; k++) {
        int lin = tid + k*256;
        int r = lin >> 5;
        int c = (lin & 31) * 4;
        float4 v = *(const float4*)(dptr + (size_t)r*Dd + dc + c);
        *(float4*)&xs[r*XSTRIDE + c] = v;
    }
}

__global__ void __launch_bounds__(256)
k_em(const float* __restrict__ data, const float* __restrict__ mask,
     float* __restrict__ out_qq) {
    extern __shared__ float smem[];
    float* xs  = smem;                       // TN * XSTRIDE
    float* as_ = smem + TN*XSTRIDE;          // DK * Pp   (A, layout [dk][p])
    float* is_ = as_ + DK*Pp;                // DK * Pp   (invS)
    float* qs  = is_ + DK*Pp;                // TN * Pp   (jll then qq)

    const int b  = blockIdx.y;
    const int n0 = blockIdx.x * TN;
    const int tid = threadIdx.x;
    const float* dptr = data + ((size_t)b*Nn + n0) * Dd;

    // ---------------- phase 1: s1 = x.(mu*invS), s2 = x^2.invS (f32x2 packed over p) ----
    // thread covers 2 n rows x 4 p (2 packed p-pairs)
    const int p0 = (tid & 3) * 4;
    const int nb = (tid >> 2) * 2;

    u64 s1[2][2], s2[2][2];
    #pragma unroll
    for (int i = 0; i < 2; i++) { s1[i][0]=s1[i][1]=s2[i][0]=s2[i][1]=0ull; }

    for (int dc = 0; dc < Dd; dc += DK) {
        load_xtile(xs, dptr, dc, tid);
        #pragma unroll
        for (int k = 0; k < 2; k++) {
            int lin = tid + k*256;           // 0..511
            int dkr = lin >> 2, c = (lin & 3) * 4;
            size_t g = ((size_t)b*Dd + dc + dkr)*Pp + c;
            *(float4*)&as_[dkr*Pp + c] = *(const float4*)&g_A[g];
            *(float4*)&is_[dkr*Pp + c] = *(const float4*)&g_I[g];
        }
        __syncthreads();

        for (int dk = 0; dk < DK; dk += 4) {
            float xr[2][4];
            #pragma unroll
            for (int i = 0; i < 2; i++)
                *(float4*)xr[i] = *(const float4*)&xs[(nb+i)*XSTRIDE + dk];
            #pragma unroll
            for (int j = 0; j < 4; j++) {
                u64 avA = *(const u64*)&as_[(dk+j)*Pp + p0];
                u64 avB = *(const u64*)&as_[(dk+j)*Pp + p0 + 2];
                u64 ivA = *(const u64*)&is_[(dk+j)*Pp + p0];
                u64 ivB = *(const u64*)&is_[(dk+j)*Pp + p0 + 2];
                #pragma unroll
                for (int i = 0; i < 2; i++) {
                    float x  = xr[i][j];
                    float x2 = x * x;
                    u64 xx  = pk2(x,  x);
                    u64 xx2 = pk2(x2, x2);
                    fma2(s1[i][0], xx,  avA);
                    fma2(s1[i][1], xx,  avB);
                    fma2(s2[i][0], xx2, ivA);
                    fma2(s2[i][1], xx2, ivB);
                }
            }
        }
        __syncthreads();
    }

    // jll into qs
    {
        #pragma unroll
        for (int a = 0; a < 2; a++) {
            float c0 = g_cst[b*Pp + p0 + 2*a];
            float c1 = g_cst[b*Pp + p0 + 2*a + 1];
            #pragma unroll
            for (int i = 0; i < 2; i++) {
                float s1l, s1h, s2l, s2h;
                upk2(s1[i][a], s1l, s1h);
                upk2(s2[i][a], s2l, s2h);
                qs[(nb+i)*Pp + p0 + 2*a    ] = c0 + s1l - 0.5f*s2l;
                qs[(nb+i)*Pp + p0 + 2*a + 1] = c1 + s1h - 0.5f*s2h;
            }
        }
    }
    __syncthreads();

    // ---------------- softmax -> qq ----------------
    if (tid < TN) {
        int n = tid;
        float v[Pp];
        float mx = -3.4e38f;
        #pragma unroll
        for (int k = 0; k < Pp; k++) { v[k] = qs[n*Pp + k]; mx = fmaxf(mx, v[k]); }
        float ssum = 0.f;
        #pragma unroll
        for (int k = 0; k < Pp; k++) { v[k] = expf(v[k] - mx); ssum += v[k]; }
        float w = mask[(size_t)b*Nn + n0 + n] / ssum;
        float* op = out_qq + ((size_t)(b*Nn + n0 + n)) * Pp;
        #pragma unroll
        for (int k = 0; k < Pp; k++) {
            float q = v[k] * w;
            qs[n*Pp + k] = q;
        }
        #pragma unroll
        for (int k = 0; k < Pp; k += 4) {
            float4 o = make_float4(qs[n*Pp+k], qs[n*Pp+k+1], qs[n*Pp+k+2], qs[n*Pp+k+3]);
            *(float4*)(op + k) = o;
        }
    }
    __syncthreads();

    // wsum partial
    if (tid < Pp) {
        float s = 0.f;
        for (int n = 0; n < TN; n++) s += qs[n*Pp + tid];
        atomicAdd(&g_wsum[b*Pp + tid], s);
    }
    __syncthreads();

    // ---------------- phase 2: wx += qq^T x, wxx += qq^T x^2 (f32x2 packed over d) ----
    const int q0 = (tid & 7) * 2;            // 2 p per thread
    const int d0 = (tid >> 3) * 4;           // 4 d-cols (2 packed pairs) per thread

    for (int dc = 0; dc < Dd; dc += DK) {
        load_xtile(xs, dptr, dc, tid);
        __syncthreads();

        u64 wx[2][2], wxx[2][2];
        #pragma unroll
        for (int a = 0; a < 2; a++)
            #pragma unroll
            for (int j = 0; j < 2; j++) { wx[a][j] = 0ull; wxx[a][j] = 0ull; }

        for (int n = 0; n < TN; n++) {
            float2 qv = *(const float2*)&qs[n*Pp + q0];
            u64 qx = pk2(qv.x, qv.x);
            u64 qy = pk2(qv.y, qv.y);
            u64 xp0 = *(const u64*)&xs[n*XSTRIDE + d0];
            u64 xp1 = *(const u64*)&xs[n*XSTRIDE + d0 + 2];
            u64 xq0 = mul2(xp0, xp0);
            u64 xq1 = mul2(xp1, xp1);
            fma2(wx[0][0],  qx, xp0);  fma2(wx[0][1],  qx, xp1);
            fma2(wx[1][0],  qy, xp0);  fma2(wx[1][1],  qy, xp1);
            fma2(wxx[0][0], qx, xq0);  fma2(wxx[0][1], qx, xq1);
            fma2(wxx[1][0], qy, xq0);  fma2(wxx[1][1], qy, xq1);
        }
        #pragma unroll
        for (int a = 0; a < 2; a++) {
            size_t base = ((size_t)(b*Pp + q0 + a))*Dd + dc + d0;
            #pragma unroll
            for (int j = 0; j < 2; j++) {
                float lo, hi;
                upk2(wx[a][j], lo, hi);
                atomicAdd(&g_wx[base + 2*j],     lo);
                atomicAdd(&g_wx[base + 2*j + 1], hi);
                upk2(wxx[a][j], lo, hi);
                atomicAdd(&g_wxx[base + 2*j],     lo);
                atomicAdd(&g_wxx[base + 2*j + 1], hi);
            }
        }
        __syncthreads();
    }
}

__global__ void k_fin(const float* __restrict__ m) {
    int idx = blockIdx.x * 256 + threadIdx.x;    // < Bt*Pp*Dd
    int b = idx / (Pp*Dd);
    int r = idx % (Pp*Dd);
    int p = r / Dd;
    float ws = g_wsum[b*Pp + p] + 1.0f;          // tau = 1
    float mu = (g_wx[idx] + m[r]) / ws;
    float Sg = (g_wxx[idx] + g_mV[r]) / ws - mu*mu;
    g_mu[idx] = mu;
    g_Sg[idx] = Sg;
    g_wx[idx]  = 0.f;
    g_wxx[idx] = 0.f;
}

__global__ void k_pik() {
    int b = blockIdx.x, t = threadIdx.x;         // 32 threads
    float v = (t < Pp) ? (g_wsum[b*Pp + t] + 1.0f) : 0.f;
    float tot = v;
    #pragma unroll
    for (int o = 16; o > 0; o >>= 1) tot += __shfl_xor_sync(0xffffffffu, tot, o);
    if (t < Pp) {
        g_pi[b*Pp + t] = v / tot;
        g_wsum[b*Pp + t] = 0.f;
    }
}

__global__ void k_out(float* __restrict__ out) {
    int idx = blockIdx.x * 256 + threadIdx.x;    // < Bt*Pp*Dd
    out[Bt*Pp + idx] = g_mu[idx];
    out[Bt*Pp + Bt*Pp*Dd + idx] = g_Sg[idx];
    if (idx < Bt*Pp) out[idx] = g_pi[idx];
}

extern "C" void kernel_launch(void* const* d_in, const int* in_sizes, int n_in,
                              void* d_out, int out_size) {
    const float* data = (const float*)d_in[0];
    const float* mask = (const float*)d_in[1];
    const float* m    = (const float*)d_in[2];
    const float* V_   = (const float*)d_in[3];
    float* out = (float*)d_out;

    const int smem_bytes = (TN*XSTRIDE + 2*DK*Pp + TN*Pp) * (int)sizeof(float); // 92160
    cudaFuncSetAttribute(k_em, cudaFuncAttributeMaxDynamicSharedMemorySize, smem_bytes);

    const int qq_off = Bt*Pp + 2*Bt*Pp*Dd;       // 262272

    k_init<<<(Pp*Dd + 255)/256, 256>>>(m, V_);
    for (int it = 0; it < ITERS; it++) {
        k_prep<<<Bt*Pp, 256>>>();
        k_em<<<dim3(NT, Bt), 256, smem_bytes>>>(data, mask, out + qq_off);
        k_fin<<<(Bt*Pp*Dd)/256, 256>>>(m);
        k_pik<<<Bt, 32>>>();
    }
    k_out<<<(Bt*Pp*Dd)/256, 256>>>(out);
}

// round 6
// speedup vs baseline: 1.0009x; 1.0009x over previous
#include <cuda_runtime.h>
#include <math.h>

#define Bt 8
#define Nn 4096
#define Dd 1024
#define Pp 16
#define ITERS 3
#define TN 128
#define DK 128
#define NT (Nn/TN)
#define XSTRIDE (DK+4)
#define LOG2PI 1.8378770664093453f

typedef unsigned long long u64;

__device__ __forceinline__ u64 pk2(float a, float b) {
    u64 r; asm("mov.b64 %0, {%1,%2};" : "=l"(r) : "f"(a), "f"(b)); return r;
}
__device__ __forceinline__ void upk2(u64 v, float& lo, float& hi) {
    asm("mov.b64 {%0,%1}, %2;" : "=f"(lo), "=f"(hi) : "l"(v));
}
__device__ __forceinline__ void fma2(u64& acc, u64 a, u64 b) {
    asm("fma.rn.f32x2 %0, %1, %2, %0;" : "+l"(acc) : "l"(a), "l"(b));
}
__device__ __forceinline__ u64 mul2(u64 a, u64 b) {
    u64 r; asm("mul.rn.f32x2 %0, %1, %2;" : "=l"(r) : "l"(a), "l"(b)); return r;
}

// persistent state / scratch (no allocations allowed)
__device__ float g_A[Bt*Dd*Pp];     // [b][d][p] = mu * invSigma
__device__ float g_I[Bt*Dd*Pp];     // [b][d][p] = invSigma
__device__ float g_cst[Bt*Pp];
__device__ float g_pi[Bt*Pp];
__device__ float g_mu[Bt*Pp*Dd];
__device__ float g_Sg[Bt*Pp*Dd];
__device__ float g_mV[Pp*Dd];       // V + m*m
__device__ float g_wsum[Bt*Pp];
__device__ float g_wx[Bt*Pp*Dd];
__device__ float g_wxx[Bt*Pp*Dd];

__global__ void k_init(const float* __restrict__ m, const float* __restrict__ V_) {
    int i = blockIdx.x * blockDim.x + threadIdx.x;
    if (i < Pp*Dd) {
        float v = 0.1f * log1pf(expf(V_[i]));   // EPS * softplus(V_)
        float mm = m[i];
        g_mV[i] = v + mm*mm;
        #pragma unroll
        for (int b = 0; b < Bt; b++) {
            g_mu[b*Pp*Dd + i] = mm;
            g_Sg[b*Pp*Dd + i] = v;
            g_wx[b*Pp*Dd + i] = 0.f;
            g_wxx[b*Pp*Dd + i] = 0.f;
        }
    }
    if (i < Bt*Pp) { g_pi[i] = 1.0f/Pp; g_wsum[i] = 0.f; }
}

__global__ void k_prep() {
    int b = blockIdx.x / Pp, p = blockIdx.x % Pp;
    __shared__ float red[256];
    float acc = 0.f;
    for (int d = threadIdx.x; d < Dd; d += 256) {
        float S  = g_Sg[(b*Pp + p)*Dd + d];
        float mu = g_mu[(b*Pp + p)*Dd + d];
        float inv = 1.0f / S;
        g_A[(b*Dd + d)*Pp + p] = mu * inv;
        g_I[(b*Dd + d)*Pp + p] = inv;
        acc += logf(S) + mu*mu*inv;
    }
    red[threadIdx.x] = acc; __syncthreads();
    for (int s = 128; s > 0; s >>= 1) {
        if (threadIdx.x < s) red[threadIdx.x] += red[threadIdx.x + s];
        __syncthreads();
    }
    if (threadIdx.x == 0)
        g_cst[b*Pp + p] = logf(g_pi[b*Pp + p]) - 0.5f * ((float)Dd * LOG2PI + red[0]);
}

__device__ __forceinline__ void load_xtile(float* xs, const float* __restrict__ dptr,
                                           int dc, int tid) {
    #pragma unroll
    for (int k = 0; k < 16; k++) {
        int lin = tid + k*256;
        int r = lin >> 5;
        int c = (lin & 31) * 4;
        float4 v = *(const float4*)(dptr + (size_t)r*Dd + dc + c);
        *(float4*)&xs[r*XSTRIDE + c] = v;
    }
}

__global__ void __launch_bounds__(256)
k_em(const float* __restrict__ data, const float* __restrict__ mask,
     float* __restrict__ out_qq) {
    extern __shared__ float smem[];
    float* xs  = smem;                       // TN * XSTRIDE
    float* as_ = smem + TN*XSTRIDE;          // DK * Pp   (A, layout [dk][p])
    float* is_ = as_ + DK*Pp;                // DK * Pp   (invS)
    float* qs  = is_ + DK*Pp;                // TN * Pp   (jll then qq)

    const int b  = blockIdx.y;
    const int n0 = blockIdx.x * TN;
    const int tid = threadIdx.x;
    const float* dptr = data + ((size_t)b*Nn + n0) * Dd;

    // ---------------- phase 1: s1 = x.(mu*invS), s2 = x^2.invS (f32x2 packed over p) ----
    // thread covers 2 n rows x 4 p (2 packed p-pairs)
    const int p0 = (tid & 3) * 4;
    const int nb = (tid >> 2) * 2;

    u64 s1[2][2], s2[2][2];
    #pragma unroll
    for (int i = 0; i < 2; i++) { s1[i][0]=s1[i][1]=s2[i][0]=s2[i][1]=0ull; }

    for (int dc = 0; dc < Dd; dc += DK) {
        load_xtile(xs, dptr, dc, tid);
        #pragma unroll
        for (int k = 0; k < 2; k++) {
            int lin = tid + k*256;           // 0..511
            int dkr = lin >> 2, c = (lin & 3) * 4;
            size_t g = ((size_t)b*Dd + dc + dkr)*Pp + c;
            *(float4*)&as_[dkr*Pp + c] = *(const float4*)&g_A[g];
            *(float4*)&is_[dkr*Pp + c] = *(const float4*)&g_I[g];
        }
        __syncthreads();

        for (int dk = 0; dk < DK; dk += 4) {
            float xr[2][4];
            #pragma unroll
            for (int i = 0; i < 2; i++)
                *(float4*)xr[i] = *(const float4*)&xs[(nb+i)*XSTRIDE + dk];
            #pragma unroll
            for (int j = 0; j < 4; j++) {
                u64 avA = *(const u64*)&as_[(dk+j)*Pp + p0];
                u64 avB = *(const u64*)&as_[(dk+j)*Pp + p0 + 2];
                u64 ivA = *(const u64*)&is_[(dk+j)*Pp + p0];
                u64 ivB = *(const u64*)&is_[(dk+j)*Pp + p0 + 2];
                #pragma unroll
                for (int i = 0; i < 2; i++) {
                    float x  = xr[i][j];
                    float x2 = x * x;
                    u64 xx  = pk2(x,  x);
                    u64 xx2 = pk2(x2, x2);
                    fma2(s1[i][0], xx,  avA);
                    fma2(s1[i][1], xx,  avB);
                    fma2(s2[i][0], xx2, ivA);
                    fma2(s2[i][1], xx2, ivB);
                }
            }
        }
        __syncthreads();
    }

    // jll into qs
    {
        #pragma unroll
        for (int a = 0; a < 2; a++) {
            float c0 = g_cst[b*Pp + p0 + 2*a];
            float c1 = g_cst[b*Pp + p0 + 2*a + 1];
            #pragma unroll
            for (int i = 0; i < 2; i++) {
                float s1l, s1h, s2l, s2h;
                upk2(s1[i][a], s1l, s1h);
                upk2(s2[i][a], s2l, s2h);
                qs[(nb+i)*Pp + p0 + 2*a    ] = c0 + s1l - 0.5f*s2l;
                qs[(nb+i)*Pp + p0 + 2*a + 1] = c1 + s1h - 0.5f*s2h;
            }
        }
    }
    __syncthreads();

    // ---------------- softmax -> qq ----------------
    if (tid < TN) {
        int n = tid;
        float v[Pp];
        float mx = -3.4e38f;
        #pragma unroll
        for (int k = 0; k < Pp; k++) { v[k] = qs[n*Pp + k]; mx = fmaxf(mx, v[k]); }
        float ssum = 0.f;
        #pragma unroll
        for (int k = 0; k < Pp; k++) { v[k] = expf(v[k] - mx); ssum += v[k]; }
        float w = mask[(size_t)b*Nn + n0 + n] / ssum;
        float* op = out_qq + ((size_t)(b*Nn + n0 + n)) * Pp;
        #pragma unroll
        for (int k = 0; k < Pp; k++) {
            float q = v[k] * w;
            qs[n*Pp + k] = q;
        }
        #pragma unroll
        for (int k = 0; k < Pp; k += 4) {
            float4 o = make_float4(qs[n*Pp+k], qs[n*Pp+k+1], qs[n*Pp+k+2], qs[n*Pp+k+3]);
            *(float4*)(op + k) = o;
        }
    }
    __syncthreads();

    // wsum partial
    if (tid < Pp) {
        float s = 0.f;
        for (int n = 0; n < TN; n++) s += qs[n*Pp + tid];
        atomicAdd(&g_wsum[b*Pp + tid], s);
    }
    __syncthreads();

    // ---------------- phase 2: wx += qq^T x, wxx += qq^T x^2 (f32x2 packed over d) ----
    const int q0 = (tid & 7) * 2;            // 2 p per thread
    const int d0 = (tid >> 3) * 4;           // 4 d-cols (2 packed pairs) per thread

    for (int dc = 0; dc < Dd; dc += DK) {
        load_xtile(xs, dptr, dc, tid);
        __syncthreads();

        u64 wx[2][2], wxx[2][2];
        #pragma unroll
        for (int a = 0; a < 2; a++)
            #pragma unroll
            for (int j = 0; j < 2; j++) { wx[a][j] = 0ull; wxx[a][j] = 0ull; }

        for (int n = 0; n < TN; n++) {
            float2 qv = *(const float2*)&qs[n*Pp + q0];
            u64 qx = pk2(qv.x, qv.x);
            u64 qy = pk2(qv.y, qv.y);
            u64 xp0 = *(const u64*)&xs[n*XSTRIDE + d0];
            u64 xp1 = *(const u64*)&xs[n*XSTRIDE + d0 + 2];
            u64 xq0 = mul2(xp0, xp0);
            u64 xq1 = mul2(xp1, xp1);
            fma2(wx[0][0],  qx, xp0);  fma2(wx[0][1],  qx, xp1);
            fma2(wx[1][0],  qy, xp0);  fma2(wx[1][1],  qy, xp1);
            fma2(wxx[0][0], qx, xq0);  fma2(wxx[0][1], qx, xq1);
            fma2(wxx[1][0], qy, xq0);  fma2(wxx[1][1], qy, xq1);
        }
        #pragma unroll
        for (int a = 0; a < 2; a++) {
            size_t base = ((size_t)(b*Pp + q0 + a))*Dd + dc + d0;
            #pragma unroll
            for (int j = 0; j < 2; j++) {
                float lo, hi;
                upk2(wx[a][j], lo, hi);
                atomicAdd(&g_wx[base + 2*j],     lo);
                atomicAdd(&g_wx[base + 2*j + 1], hi);
                upk2(wxx[a][j], lo, hi);
                atomicAdd(&g_wxx[base + 2*j],     lo);
                atomicAdd(&g_wxx[base + 2*j + 1], hi);
            }
        }
        __syncthreads();
    }
}

__global__ void k_fin(const float* __restrict__ m) {
    int idx = blockIdx.x * 256 + threadIdx.x;    // < Bt*Pp*Dd
    int b = idx / (Pp*Dd);
    int r = idx % (Pp*Dd);
    int p = r / Dd;
    float ws = g_wsum[b*Pp + p] + 1.0f;          // tau = 1
    float mu = (g_wx[idx] + m[r]) / ws;
    float Sg = (g_wxx[idx] + g_mV[r]) / ws - mu*mu;
    g_mu[idx] = mu;
    g_Sg[idx] = Sg;
    g_wx[idx]  = 0.f;
    g_wxx[idx] = 0.f;
}

__global__ void k_pik() {
    int b = blockIdx.x, t = threadIdx.x;         // 32 threads
    float v = (t < Pp) ? (g_wsum[b*Pp + t] + 1.0f) : 0.f;
    float tot = v;
    #pragma unroll
    for (int o = 16; o > 0; o >>= 1) tot += __shfl_xor_sync(0xffffffffu, tot, o);
    if (t < Pp) {
        g_pi[b*Pp + t] = v / tot;
        g_wsum[b*Pp + t] = 0.f;
    }
}

__global__ void k_out(float* __restrict__ out) {
    int idx = blockIdx.x * 256 + threadIdx.x;    // < Bt*Pp*Dd
    out[Bt*Pp + idx] = g_mu[idx];
    out[Bt*Pp + Bt*Pp*Dd + idx] = g_Sg[idx];
    if (idx < Bt*Pp) out[idx] = g_pi[idx];
}

extern "C" void kernel_launch(void* const* d_in, const int* in_sizes, int n_in,
                              void* d_out, int out_size) {
    const float* data = (const float*)d_in[0];
    const float* mask = (const float*)d_in[1];
    const float* m    = (const float*)d_in[2];
    const float* V_   = (const float*)d_in[3];
    float* out = (float*)d_out;

    const int smem_bytes = (TN*XSTRIDE + 2*DK*Pp + TN*Pp) * (int)sizeof(float); // 92160
    cudaFuncSetAttribute(k_em, cudaFuncAttributeMaxDynamicSharedMemorySize, smem_bytes);

    const int qq_off = Bt*Pp + 2*Bt*Pp*Dd;       // 262272

    k_init<<<(Pp*Dd + 255)/256, 256>>>(m, V_);
    for (int it = 0; it < ITERS; it++) {
        k_prep<<<Bt*Pp, 256>>>();
        k_em<<<dim3(NT, Bt), 256, smem_bytes>>>(data, mask, out + qq_off);
        k_fin<<<(Bt*Pp*Dd)/256, 256>>>(m);
        k_pik<<<Bt, 32>>>();
    }
    k_out<<<(Bt*Pp*Dd)/256, 256>>>(out);
}

// round 7
// speedup vs baseline: 1.0028x; 1.0019x over previous
#include <cuda_runtime.h>
#include <math.h>

#define Bt 8
#define Nn 4096
#define Dd 1024
#define Pp 16
#define ITERS 3
#define TN 128
#define DK 128
#define NT (Nn/TN)
#define XSTRIDE (DK+4)
#define LOG2PI 1.8378770664093453f

typedef unsigned long long u64;

__device__ __forceinline__ u64 pk2(float a, float b) {
    u64 r; asm("mov.b64 %0, {%1,%2};" : "=l"(r) : "f"(a), "f"(b)); return r;
}
__device__ __forceinline__ void upk2(u64 v, float& lo, float& hi) {
    asm("mov.b64 {%0,%1}, %2;" : "=f"(lo), "=f"(hi) : "l"(v));
}
__device__ __forceinline__ void fma2(u64& acc, u64 a, u64 b) {
    asm("fma.rn.f32x2 %0, %1, %2, %0;" : "+l"(acc) : "l"(a), "l"(b));
}
__device__ __forceinline__ u64 mul2(u64 a, u64 b) {
    u64 r; asm("mul.rn.f32x2 %0, %1, %2;" : "=l"(r) : "l"(a), "l"(b)); return r;
}

// persistent state / scratch (no allocations allowed)
__device__ float g_A[Bt*Dd*Pp];     // [b][d][p] = mu * invSigma
__device__ float g_I[Bt*Dd*Pp];     // [b][d][p] = invSigma
__device__ float g_cst[Bt*Pp];
__device__ float g_pi[Bt*Pp];
__device__ float g_mu[Bt*Pp*Dd];
__device__ float g_Sg[Bt*Pp*Dd];
__device__ float g_mV[Pp*Dd];       // V + m*m
__device__ float g_wsum[Bt*Pp];
__device__ float g_wx[Bt*Pp*Dd];
__device__ float g_wxx[Bt*Pp*Dd];

__global__ void k_init(const float* __restrict__ m, const float* __restrict__ V_) {
    int i = blockIdx.x * blockDim.x + threadIdx.x;
    if (i < Pp*Dd) {
        float v = 0.1f * log1pf(expf(V_[i]));   // EPS * softplus(V_)
        float mm = m[i];
        g_mV[i] = v + mm*mm;
        #pragma unroll
        for (int b = 0; b < Bt; b++) {
            g_mu[b*Pp*Dd + i] = mm;
            g_Sg[b*Pp*Dd + i] = v;
            g_wx[b*Pp*Dd + i] = 0.f;
            g_wxx[b*Pp*Dd + i] = 0.f;
        }
    }
    if (i < Bt*Pp) { g_pi[i] = 1.0f/Pp; g_wsum[i] = 0.f; }
}

__global__ void k_prep() {
    int b = blockIdx.x / Pp, p = blockIdx.x % Pp;
    __shared__ float red[256];
    float acc = 0.f;
    for (int d = threadIdx.x; d < Dd; d += 256) {
        float S  = g_Sg[(b*Pp + p)*Dd + d];
        float mu = g_mu[(b*Pp + p)*Dd + d];
        float inv = 1.0f / S;
        g_A[(b*Dd + d)*Pp + p] = mu * inv;
        g_I[(b*Dd + d)*Pp + p] = inv;
        acc += logf(S) + mu*mu*inv;
    }
    red[threadIdx.x] = acc; __syncthreads();
    for (int s = 128; s > 0; s >>= 1) {
        if (threadIdx.x < s) red[threadIdx.x] += red[threadIdx.x + s];
        __syncthreads();
    }
    if (threadIdx.x == 0)
        g_cst[b*Pp + p] = logf(g_pi[b*Pp + p]) - 0.5f * ((float)Dd * LOG2PI + red[0]);
}

__device__ __forceinline__ void load_xtile(float* xs, const float* __restrict__ dptr,
                                           int dc, int tid) {
    #pragma unroll
    for (int k = 0; k < 16; k++) {
        int lin = tid + k*256;
        int r = lin >> 5;
        int c = (lin & 31) * 4;
        float4 v = *(const float4*)(dptr + (size_t)r*Dd + dc + c);
        *(float4*)&xs[r*XSTRIDE + c] = v;
    }
}

__global__ void __launch_bounds__(256)
k_em(const float* __restrict__ data, const float* __restrict__ mask,
     float* __restrict__ out_qq) {
    extern __shared__ float smem[];
    float* xs  = smem;                       // TN * XSTRIDE
    float* as_ = smem + TN*XSTRIDE;          // DK * Pp   (A, layout [dk][p])
    float* is_ = as_ + DK*Pp;                // DK * Pp   (invS)
    float* qs  = is_ + DK*Pp;                // TN * Pp   (jll then qq)

    const int b  = blockIdx.y;
    const int n0 = blockIdx.x * TN;
    const int tid = threadIdx.x;
    const float* dptr = data + ((size_t)b*Nn + n0) * Dd;

    // ---------------- phase 1: s1 = x.(mu*invS), s2 = x^2.invS (f32x2 packed over p) ----
    // thread covers 2 n rows x 4 p (2 packed p-pairs)
    const int p0 = (tid & 3) * 4;
    const int nb = (tid >> 2) * 2;

    u64 s1[2][2], s2[2][2];
    #pragma unroll
    for (int i = 0; i < 2; i++) { s1[i][0]=s1[i][1]=s2[i][0]=s2[i][1]=0ull; }

    for (int dc = 0; dc < Dd; dc += DK) {
        load_xtile(xs, dptr, dc, tid);
        #pragma unroll
        for (int k = 0; k < 2; k++) {
            int lin = tid + k*256;           // 0..511
            int dkr = lin >> 2, c = (lin & 3) * 4;
            size_t g = ((size_t)b*Dd + dc + dkr)*Pp + c;
            *(float4*)&as_[dkr*Pp + c] = *(const float4*)&g_A[g];
            *(float4*)&is_[dkr*Pp + c] = *(const float4*)&g_I[g];
        }
        __syncthreads();

        for (int dk = 0; dk < DK; dk += 4) {
            float xr[2][4];
            #pragma unroll
            for (int i = 0; i < 2; i++)
                *(float4*)xr[i] = *(const float4*)&xs[(nb+i)*XSTRIDE + dk];
            #pragma unroll
            for (int j = 0; j < 4; j++) {
                u64 avA = *(const u64*)&as_[(dk+j)*Pp + p0];
                u64 avB = *(const u64*)&as_[(dk+j)*Pp + p0 + 2];
                u64 ivA = *(const u64*)&is_[(dk+j)*Pp + p0];
                u64 ivB = *(const u64*)&is_[(dk+j)*Pp + p0 + 2];
                #pragma unroll
                for (int i = 0; i < 2; i++) {
                    float x  = xr[i][j];
                    float x2 = x * x;
                    u64 xx  = pk2(x,  x);
                    u64 xx2 = pk2(x2, x2);
                    fma2(s1[i][0], xx,  avA);
                    fma2(s1[i][1], xx,  avB);
                    fma2(s2[i][0], xx2, ivA);
                    fma2(s2[i][1], xx2, ivB);
                }
            }
        }
        __syncthreads();
    }

    // jll into qs
    {
        #pragma unroll
        for (int a = 0; a < 2; a++) {
            float c0 = g_cst[b*Pp + p0 + 2*a];
            float c1 = g_cst[b*Pp + p0 + 2*a + 1];
            #pragma unroll
            for (int i = 0; i < 2; i++) {
                float s1l, s1h, s2l, s2h;
                upk2(s1[i][a], s1l, s1h);
                upk2(s2[i][a], s2l, s2h);
                qs[(nb+i)*Pp + p0 + 2*a    ] = c0 + s1l - 0.5f*s2l;
                qs[(nb+i)*Pp + p0 + 2*a + 1] = c1 + s1h - 0.5f*s2h;
            }
        }
    }
    __syncthreads();

    // ---------------- softmax -> qq ----------------
    if (tid < TN) {
        int n = tid;
        float v[Pp];
        float mx = -3.4e38f;
        #pragma unroll
        for (int k = 0; k < Pp; k++) { v[k] = qs[n*Pp + k]; mx = fmaxf(mx, v[k]); }
        float ssum = 0.f;
        #pragma unroll
        for (int k = 0; k < Pp; k++) { v[k] = expf(v[k] - mx); ssum += v[k]; }
        float w = mask[(size_t)b*Nn + n0 + n] / ssum;
        float* op = out_qq + ((size_t)(b*Nn + n0 + n)) * Pp;
        #pragma unroll
        for (int k = 0; k < Pp; k++) {
            float q = v[k] * w;
            qs[n*Pp + k] = q;
        }
        #pragma unroll
        for (int k = 0; k < Pp; k += 4) {
            float4 o = make_float4(qs[n*Pp+k], qs[n*Pp+k+1], qs[n*Pp+k+2], qs[n*Pp+k+3]);
            *(float4*)(op + k) = o;
        }
    }
    __syncthreads();

    // wsum partial
    if (tid < Pp) {
        float s = 0.f;
        for (int n = 0; n < TN; n++) s += qs[n*Pp + tid];
        atomicAdd(&g_wsum[b*Pp + tid], s);
    }
    __syncthreads();

    // ---------------- phase 2: wx += qq^T x, wxx += qq^T x^2 (f32x2 packed over d) ----
    const int q0 = (tid & 7) * 2;            // 2 p per thread
    const int d0 = (tid >> 3) * 4;           // 4 d-cols (2 packed pairs) per thread

    for (int dc = 0; dc < Dd; dc += DK) {
        load_xtile(xs, dptr, dc, tid);
        __syncthreads();

        u64 wx[2][2], wxx[2][2];
        #pragma unroll
        for (int a = 0; a < 2; a++)
            #pragma unroll
            for (int j = 0; j < 2; j++) { wx[a][j] = 0ull; wxx[a][j] = 0ull; }

        for (int n = 0; n < TN; n++) {
            float2 qv = *(const float2*)&qs[n*Pp + q0];
            u64 qx = pk2(qv.x, qv.x);
            u64 qy = pk2(qv.y, qv.y);
            u64 xp0 = *(const u64*)&xs[n*XSTRIDE + d0];
            u64 xp1 = *(const u64*)&xs[n*XSTRIDE + d0 + 2];
            u64 xq0 = mul2(xp0, xp0);
            u64 xq1 = mul2(xp1, xp1);
            fma2(wx[0][0],  qx, xp0);  fma2(wx[0][1],  qx, xp1);
            fma2(wx[1][0],  qy, xp0);  fma2(wx[1][1],  qy, xp1);
            fma2(wxx[0][0], qx, xq0);  fma2(wxx[0][1], qx, xq1);
            fma2(wxx[1][0], qy, xq0);  fma2(wxx[1][1], qy, xq1);
        }
        #pragma unroll
        for (int a = 0; a < 2; a++) {
            size_t base = ((size_t)(b*Pp + q0 + a))*Dd + dc + d0;
            #pragma unroll
            for (int j = 0; j < 2; j++) {
                float lo, hi;
                upk2(wx[a][j], lo, hi);
                atomicAdd(&g_wx[base + 2*j],     lo);
                atomicAdd(&g_wx[base + 2*j + 1], hi);
                upk2(wxx[a][j], lo, hi);
                atomicAdd(&g_wxx[base + 2*j],     lo);
                atomicAdd(&g_wxx[base + 2*j + 1], hi);
            }
        }
        __syncthreads();
    }
}

__global__ void k_fin(const float* __restrict__ m) {
    int idx = blockIdx.x * 256 + threadIdx.x;    // < Bt*Pp*Dd
    int b = idx / (Pp*Dd);
    int r = idx % (Pp*Dd);
    int p = r / Dd;
    float ws = g_wsum[b*Pp + p] + 1.0f;          // tau = 1
    float mu = (g_wx[idx] + m[r]) / ws;
    float Sg = (g_wxx[idx] + g_mV[r]) / ws - mu*mu;
    g_mu[idx] = mu;
    g_Sg[idx] = Sg;
    g_wx[idx]  = 0.f;
    g_wxx[idx] = 0.f;
}

__global__ void k_pik() {
    int b = blockIdx.x, t = threadIdx.x;         // 32 threads
    float v = (t < Pp) ? (g_wsum[b*Pp + t] + 1.0f) : 0.f;
    float tot = v;
    #pragma unroll
    for (int o = 16; o > 0; o >>= 1) tot += __shfl_xor_sync(0xffffffffu, tot, o);
    if (t < Pp) {
        g_pi[b*Pp + t] = v / tot;
        g_wsum[b*Pp + t] = 0.f;
    }
}

__global__ void k_out(float* __restrict__ out) {
    int idx = blockIdx.x * 256 + threadIdx.x;    // < Bt*Pp*Dd
    out[Bt*Pp + idx] = g_mu[idx];
    out[Bt*Pp + Bt*Pp*Dd + idx] = g_Sg[idx];
    if (idx < Bt*Pp) out[idx] = g_pi[idx];
}

extern "C" void kernel_launch(void* const* d_in, const int* in_sizes, int n_in,
                              void* d_out, int out_size) {
    const float* data = (const float*)d_in[0];
    const float* mask = (const float*)d_in[1];
    const float* m    = (const float*)d_in[2];
    const float* V_   = (const float*)d_in[3];
    float* out = (float*)d_out;

    const int smem_bytes = (TN*XSTRIDE + 2*DK*Pp + TN*Pp) * (int)sizeof(float); // 92160
    cudaFuncSetAttribute(k_em, cudaFuncAttributeMaxDynamicSharedMemorySize, smem_bytes);

    const int qq_off = Bt*Pp + 2*Bt*Pp*Dd;       // 262272

    k_init<<<(Pp*Dd + 255)/256, 256>>>(m, V_);
    for (int it = 0; it < ITERS; it++) {
        k_prep<<<Bt*Pp, 256>>>();
        k_em<<<dim3(NT, Bt), 256, smem_bytes>>>(data, mask, out + qq_off);
        k_fin<<<(Bt*Pp*Dd)/256, 256>>>(m);
        k_pik<<<Bt, 32>>>();
    }
    k_out<<<(Bt*Pp*Dd)/256, 256>>>(out);
}